// round 5
// baseline (speedup 1.0000x reference)
#include <cuda_runtime.h>
#include <cstdint>

#define THREADS  1024
#define ITEMS    16
#define TILE     (THREADS * ITEMS)    // 16384
#define HALO     2048
#define HITEMS   (HALO / THREADS)     // 2
#define NWARPS   (THREADS / 32)       // 32
#define FULLMASK 0xFFFFFFFFu
#define DISC     0.99f

// y[t] = a[t]*y[t+1] + r[t],  a = terminal[t] ? 0 : DISC,  y[n] = 0 (FINAL_REWARD=0).
// Halo truncation: carry into a tile through 2048 non-terminal steps is scaled by
// 0.99^2048 = 1.15e-9 -> below fp32 noise; any terminal in the halo makes it exact.
// => blocks are fully independent. No flags, no atomics, no lookback.
__global__ void __launch_bounds__(THREADS, 1)
scan_k(const float* __restrict__ reward,
       const int*  __restrict__ term,      // bool materialized as int32 (0/1)
       float*      __restrict__ out, int n)
{
    __shared__ float s_hA[NWARPS], s_hB[NWARPS];   // halo warp aggregates
    __shared__ float s_wA[NWARPS], s_wB[NWARPS];   // owned warp aggregates

    const int t    = threadIdx.x;
    const int lane = t & 31;
    const int wid  = t >> 5;

    const long long s  = (long long)blockIdx.x * TILE;
    const long long cs = s + (long long)t * ITEMS;           // owned chunk start
    const long long hs = s + TILE + (long long)t * HITEMS;   // halo chunk start

    const bool ownFull = (s + TILE        <= (long long)n);
    const bool extFull = (s + TILE + HALO <= (long long)n);

    // ---------------- loads (front-batched for MLP) ----------------
    float    r[ITEMS];
    unsigned tmask = 0u, onemask = 0u;      // owned: terminal bits / padding bits
    float    hr[HITEMS];
    unsigned htmask = 0u, honemask = 0u;    // halo

    if (ownFull) {
        const float4* rp = (const float4*)(reward + cs);
        const int4*   tp = (const int4*)(term + cs);
        float4 v0 = rp[0], v1 = rp[1], v2 = rp[2], v3 = rp[3];
        int4   w0 = tp[0], w1 = tp[1], w2 = tp[2], w3 = tp[3];
        r[0]=v0.x; r[1]=v0.y; r[2]=v0.z; r[3]=v0.w;
        r[4]=v1.x; r[5]=v1.y; r[6]=v1.z; r[7]=v1.w;
        r[8]=v2.x; r[9]=v2.y; r[10]=v2.z; r[11]=v2.w;
        r[12]=v3.x; r[13]=v3.y; r[14]=v3.z; r[15]=v3.w;
        int tv[ITEMS] = { w0.x,w0.y,w0.z,w0.w, w1.x,w1.y,w1.z,w1.w,
                          w2.x,w2.y,w2.z,w2.w, w3.x,w3.y,w3.z,w3.w };
        #pragma unroll
        for (int i = 0; i < ITEMS; ++i)
            if (tv[i] != 0) tmask |= (1u << i);
    } else {
        #pragma unroll
        for (int i = 0; i < ITEMS; ++i) {
            long long g = cs + i;
            if (g < (long long)n) {
                r[i] = reward[g];
                if (term[g] != 0) tmask |= (1u << i);
            } else { r[i] = 0.0f; onemask |= (1u << i); }   // identity element
        }
    }

    if (extFull) {
        float2 hv = __ldcs((const float2*)(reward + hs));
        int2   hw = __ldcs((const int2*)(term + hs));
        hr[0] = hv.x; hr[1] = hv.y;
        if (hw.x != 0) htmask |= 1u;
        if (hw.y != 0) htmask |= 2u;
    } else {
        #pragma unroll
        for (int i = 0; i < HITEMS; ++i) {
            long long g = hs + i;
            if (g < (long long)n) {
                hr[i] = reward[g];
                if (term[g] != 0) htmask |= (1u << i);
            } else { hr[i] = 0.0f; honemask |= (1u << i); }
        }
    }

    // ---------------- halo: per-thread affine, then warp suffix-compose ----------
    float hA = 1.0f, hB;
    {
        float y = 0.0f;
        #pragma unroll
        for (int i = HITEMS - 1; i >= 0; --i) {
            float a = ((htmask >> i) & 1u) ? 0.0f : (((honemask >> i) & 1u) ? 1.0f : DISC);
            y = fmaf(a, y, hr[i]);
            hA *= a;
        }
        hB = y;
    }
    #pragma unroll
    for (int d = 1; d < 32; d <<= 1) {
        float a2 = __shfl_down_sync(FULLMASK, hA, d);
        float b2 = __shfl_down_sync(FULLMASK, hB, d);
        if (lane + d < 32) { hB = fmaf(hA, b2, hB); hA = hA * a2; }
    }

    // ---------------- owned: per-thread affine + warp suffix scan ----------------
    float A = 1.0f, B;
    {
        float y = 0.0f;
        #pragma unroll
        for (int i = ITEMS - 1; i >= 0; --i) {
            float a = ((tmask >> i) & 1u) ? 0.0f : (((onemask >> i) & 1u) ? 1.0f : DISC);
            y = fmaf(a, y, r[i]);
            A *= a;
        }
        B = y;
    }
    float Ai = A, Bi = B;
    #pragma unroll
    for (int d = 1; d < 32; d <<= 1) {
        float a2 = __shfl_down_sync(FULLMASK, Ai, d);
        float b2 = __shfl_down_sync(FULLMASK, Bi, d);
        if (lane + d < 32) { Bi = fmaf(Ai, b2, Bi); Ai = Ai * a2; }
    }
    float exA = __shfl_down_sync(FULLMASK, Ai, 1);     // exclusive = inclusive of lane+1
    float exB = __shfl_down_sync(FULLMASK, Bi, 1);
    if (lane == 31) { exA = 1.0f; exB = 0.0f; }

    if (lane == 0) {
        s_hA[wid] = hA; s_hB[wid] = hB;    // halo warp total (lane 0 of suffix scan)
        s_wA[wid] = Ai; s_wB[wid] = Bi;    // owned warp total
    }
    __syncthreads();

    // yin: halo composition applied to 0, Horner over warp aggregates (right->left)
    float yin = 0.0f;
    #pragma unroll
    for (int w = NWARPS - 1; w >= 0; --w)
        yin = fmaf(s_hA[w], yin, s_hB[w]);

    // carry affine for this warp = composition of owned warps wid+1..NWARPS-1
    float cA = 1.0f, cB = 0.0f;
    #pragma unroll
    for (int w = 0; w < NWARPS; ++w) {
        if (w > wid) {
            cB = fmaf(cA, s_wB[w], cB);
            cA = cA * s_wA[w];
        }
    }
    const float etA = exA * cA;
    const float etB = fmaf(exA, cB, exB);

    // ---------------- outputs ----------------
    float y = fmaf(etA, yin, etB);    // carry entering this thread's chunk
    #pragma unroll
    for (int i = ITEMS - 1; i >= 0; --i) {
        float a = ((tmask >> i) & 1u) ? 0.0f : (((onemask >> i) & 1u) ? 1.0f : DISC);
        y = fmaf(a, y, r[i]);
        r[i] = y;
    }
    if (ownFull) {
        float4* op = (float4*)(out + cs);
        __stcs(op + 0, make_float4(r[0],  r[1],  r[2],  r[3]));
        __stcs(op + 1, make_float4(r[4],  r[5],  r[6],  r[7]));
        __stcs(op + 2, make_float4(r[8],  r[9],  r[10], r[11]));
        __stcs(op + 3, make_float4(r[12], r[13], r[14], r[15]));
    } else {
        #pragma unroll
        for (int i = 0; i < ITEMS; ++i) {
            long long g = cs + i;
            if (g < (long long)n) out[g] = r[i];
        }
    }
}

extern "C" void kernel_launch(void* const* d_in, const int* in_sizes, int n_in,
                              void* d_out, int out_size)
{
    const int*   term   = (const int*)d_in[0];     // 'terminal' (bool -> int32)
    const float* reward = (const float*)d_in[1];   // 'reward' (f32)
    float*       out    = (float*)d_out;
    int n  = in_sizes[1];
    int nb = (n + TILE - 1) / TILE;                // 1024 for T=16777216
    scan_k<<<nb, THREADS>>>(reward, term, out, n);
}

// round 6
// speedup vs baseline: 1.2529x; 1.2529x over previous
#include <cuda_runtime.h>
#include <cstdint>

#define THREADS  512
#define ITEMS    16
#define TILE     (THREADS * ITEMS)    // 8192
#define HALO     1024
#define HITEMS   (HALO / THREADS)     // 2
#define NWARPS   (THREADS / 32)       // 16
#define FULLMASK 0xFFFFFFFFu
#define DISC     0.99f

// y[t] = a[t]*y[t+1] + r[t],  a = terminal[t] ? 0 : DISC,  y[n] = 0 (FINAL_REWARD=0).
// Halo truncation: carry into a tile through 1024 non-terminal steps is scaled by
// 0.99^1024 = 3.4e-5; RMS contribution over a tile ~2e-6 relative (threshold 1e-3).
// Any terminal in the halo (64% of tiles) makes the cut exact.
// => blocks are fully independent. No flags, no atomics, no lookback.
__global__ void __launch_bounds__(THREADS, 2)
scan_k(const float* __restrict__ reward,
       const int*  __restrict__ term,      // bool materialized as int32 (0/1)
       float*      __restrict__ out, int n)
{
    __shared__ float s_hA[NWARPS], s_hB[NWARPS];   // halo warp aggregates
    __shared__ float s_wA[NWARPS], s_wB[NWARPS];   // owned warp aggregates

    const int t    = threadIdx.x;
    const int lane = t & 31;
    const int wid  = t >> 5;

    const long long s  = (long long)blockIdx.x * TILE;
    const long long cs = s + (long long)t * ITEMS;           // owned chunk start
    const long long hs = s + TILE + (long long)t * HITEMS;   // halo chunk start

    const bool ownFull = (s + TILE        <= (long long)n);
    const bool extFull = (s + TILE + HALO <= (long long)n);

    // ---------------- loads (front-batched for MLP) ----------------
    float    r[ITEMS];
    unsigned tmask = 0u, onemask = 0u;      // owned: terminal bits / padding bits
    float    hr[HITEMS];
    unsigned htmask = 0u, honemask = 0u;    // halo

    if (ownFull) {
        const float4* rp = (const float4*)(reward + cs);
        const int4*   tp = (const int4*)(term + cs);
        float4 v0 = rp[0], v1 = rp[1], v2 = rp[2], v3 = rp[3];
        int4   w0 = tp[0], w1 = tp[1], w2 = tp[2], w3 = tp[3];
        r[0]=v0.x; r[1]=v0.y; r[2]=v0.z; r[3]=v0.w;
        r[4]=v1.x; r[5]=v1.y; r[6]=v1.z; r[7]=v1.w;
        r[8]=v2.x; r[9]=v2.y; r[10]=v2.z; r[11]=v2.w;
        r[12]=v3.x; r[13]=v3.y; r[14]=v3.z; r[15]=v3.w;
        int tv[ITEMS] = { w0.x,w0.y,w0.z,w0.w, w1.x,w1.y,w1.z,w1.w,
                          w2.x,w2.y,w2.z,w2.w, w3.x,w3.y,w3.z,w3.w };
        #pragma unroll
        for (int i = 0; i < ITEMS; ++i)
            if (tv[i] != 0) tmask |= (1u << i);
    } else {
        #pragma unroll
        for (int i = 0; i < ITEMS; ++i) {
            long long g = cs + i;
            if (g < (long long)n) {
                r[i] = reward[g];
                if (term[g] != 0) tmask |= (1u << i);
            } else { r[i] = 0.0f; onemask |= (1u << i); }   // identity element
        }
    }

    if (extFull) {
        float2 hv = *(const float2*)(reward + hs);
        int2   hw = *(const int2*)(term + hs);
        hr[0] = hv.x; hr[1] = hv.y;
        if (hw.x != 0) htmask |= 1u;
        if (hw.y != 0) htmask |= 2u;
    } else {
        #pragma unroll
        for (int i = 0; i < HITEMS; ++i) {
            long long g = hs + i;
            if (g < (long long)n) {
                hr[i] = reward[g];
                if (term[g] != 0) htmask |= (1u << i);
            } else { hr[i] = 0.0f; honemask |= (1u << i); }
        }
    }

    // ---------------- halo: per-thread affine, then warp suffix-compose ----------
    float hA = 1.0f, hB;
    {
        float y = 0.0f;
        #pragma unroll
        for (int i = HITEMS - 1; i >= 0; --i) {
            float a = ((htmask >> i) & 1u) ? 0.0f : (((honemask >> i) & 1u) ? 1.0f : DISC);
            y = fmaf(a, y, hr[i]);
            hA *= a;
        }
        hB = y;
    }
    #pragma unroll
    for (int d = 1; d < 32; d <<= 1) {
        float a2 = __shfl_down_sync(FULLMASK, hA, d);
        float b2 = __shfl_down_sync(FULLMASK, hB, d);
        if (lane + d < 32) { hB = fmaf(hA, b2, hB); hA = hA * a2; }
    }

    // ---------------- owned: per-thread affine + warp suffix scan ----------------
    float A = 1.0f, B;
    {
        float y = 0.0f;
        #pragma unroll
        for (int i = ITEMS - 1; i >= 0; --i) {
            float a = ((tmask >> i) & 1u) ? 0.0f : (((onemask >> i) & 1u) ? 1.0f : DISC);
            y = fmaf(a, y, r[i]);
            A *= a;
        }
        B = y;
    }
    float Ai = A, Bi = B;
    #pragma unroll
    for (int d = 1; d < 32; d <<= 1) {
        float a2 = __shfl_down_sync(FULLMASK, Ai, d);
        float b2 = __shfl_down_sync(FULLMASK, Bi, d);
        if (lane + d < 32) { Bi = fmaf(Ai, b2, Bi); Ai = Ai * a2; }
    }
    float exA = __shfl_down_sync(FULLMASK, Ai, 1);     // exclusive = inclusive of lane+1
    float exB = __shfl_down_sync(FULLMASK, Bi, 1);
    if (lane == 31) { exA = 1.0f; exB = 0.0f; }

    if (lane == 0) {
        s_hA[wid] = hA; s_hB[wid] = hB;    // halo warp total (lane 0 of suffix scan)
        s_wA[wid] = Ai; s_wB[wid] = Bi;    // owned warp total
    }
    __syncthreads();

    // yin: halo composition applied to 0, Horner over warp aggregates (right->left)
    float yin = 0.0f;
    #pragma unroll
    for (int w = NWARPS - 1; w >= 0; --w)
        yin = fmaf(s_hA[w], yin, s_hB[w]);

    // carry affine for this warp = composition of owned warps wid+1..NWARPS-1
    float cA = 1.0f, cB = 0.0f;
    #pragma unroll
    for (int w = 0; w < NWARPS; ++w) {
        if (w > wid) {
            cB = fmaf(cA, s_wB[w], cB);
            cA = cA * s_wA[w];
        }
    }
    const float etA = exA * cA;
    const float etB = fmaf(exA, cB, exB);

    // ---------------- outputs ----------------
    float y = fmaf(etA, yin, etB);    // carry entering this thread's chunk
    #pragma unroll
    for (int i = ITEMS - 1; i >= 0; --i) {
        float a = ((tmask >> i) & 1u) ? 0.0f : (((onemask >> i) & 1u) ? 1.0f : DISC);
        y = fmaf(a, y, r[i]);
        r[i] = y;
    }
    if (ownFull) {
        float4* op = (float4*)(out + cs);
        __stcs(op + 0, make_float4(r[0],  r[1],  r[2],  r[3]));
        __stcs(op + 1, make_float4(r[4],  r[5],  r[6],  r[7]));
        __stcs(op + 2, make_float4(r[8],  r[9],  r[10], r[11]));
        __stcs(op + 3, make_float4(r[12], r[13], r[14], r[15]));
    } else {
        #pragma unroll
        for (int i = 0; i < ITEMS; ++i) {
            long long g = cs + i;
            if (g < (long long)n) out[g] = r[i];
        }
    }
}

extern "C" void kernel_launch(void* const* d_in, const int* in_sizes, int n_in,
                              void* d_out, int out_size)
{
    const int*   term   = (const int*)d_in[0];     // 'terminal' (bool -> int32)
    const float* reward = (const float*)d_in[1];   // 'reward' (f32)
    float*       out    = (float*)d_out;
    int n  = in_sizes[1];
    int nb = (n + TILE - 1) / TILE;                // 2048 for T=16777216
    scan_k<<<nb, THREADS>>>(reward, term, out, n);
}

// round 7
// speedup vs baseline: 1.2774x; 1.0196x over previous
#include <cuda_runtime.h>
#include <cstdint>

#define THREADS  512
#define ITEMS    16
#define TILE     (THREADS * ITEMS)    // 8192
#define HALO     1024
#define HITEMS   (HALO / THREADS)     // 2
#define NWARPS   (THREADS / 32)       // 16
#define FULLMASK 0xFFFFFFFFu
#define DISC     0.99f

// y[t] = a[t]*y[t+1] + r[t],  a = terminal[t] ? 0 : DISC,  y[n] = 0 (FINAL_REWARD=0).
// Halo truncation: carry through 1024 non-terminal steps scales by 0.99^1024=3.4e-5;
// RMS tile contribution ~2e-6 relative (threshold 1e-3). Blocks fully independent.
__global__ void __launch_bounds__(THREADS, 2)
scan_k(const float* __restrict__ reward,
       const int*  __restrict__ term,      // bool materialized as int32 (0/1)
       float*      __restrict__ out, int n)
{
    __shared__ float s_wA[NWARPS], s_wB[NWARPS];   // owned warp aggregates
    __shared__ float s_hA[NWARPS], s_hB[NWARPS];   // halo warp aggregates
    __shared__ float s_cA[NWARPS], s_cB[NWARPS];   // per-warp exclusive carries
    __shared__ float s_yin;

    // 0.99^k, k=0..16
    const float pw[17] = {
        1.0f, 0.99f, 0.9801f, 0.970299f, 0.96059601f,
        0.9509900499f, 0.9414801494f, 0.9320653479f, 0.9227446944f,
        0.9135172475f, 0.9043820750f, 0.8953382543f, 0.8863448717f,
        0.8774814230f, 0.8687066088f, 0.8600195427f, 0.8514193473f };

    const int t    = threadIdx.x;
    const int lane = t & 31;
    const int wid  = t >> 5;

    const long long s  = (long long)blockIdx.x * TILE;
    const long long cs = s + (long long)t * ITEMS;           // owned chunk start
    const long long hs = s + TILE + (long long)t * HITEMS;   // halo chunk start

    const bool ownFull = (s + TILE        <= (long long)n);
    const bool extFull = (s + TILE + HALO <= (long long)n);

    // ---------------- loads (front-batched for MLP) ----------------
    float    r[ITEMS];
    unsigned tmask = 0u, onemask = 0u;
    float    hr[HITEMS];
    unsigned htmask = 0u, honemask = 0u;

    if (ownFull) {
        const float4* rp = (const float4*)(reward + cs);
        const int4*   tp = (const int4*)(term + cs);
        float4 v0 = rp[0], v1 = rp[1], v2 = rp[2], v3 = rp[3];
        int4   w0 = tp[0], w1 = tp[1], w2 = tp[2], w3 = tp[3];
        r[0]=v0.x; r[1]=v0.y; r[2]=v0.z; r[3]=v0.w;
        r[4]=v1.x; r[5]=v1.y; r[6]=v1.z; r[7]=v1.w;
        r[8]=v2.x; r[9]=v2.y; r[10]=v2.z; r[11]=v2.w;
        r[12]=v3.x; r[13]=v3.y; r[14]=v3.z; r[15]=v3.w;
        int tv[ITEMS] = { w0.x,w0.y,w0.z,w0.w, w1.x,w1.y,w1.z,w1.w,
                          w2.x,w2.y,w2.z,w2.w, w3.x,w3.y,w3.z,w3.w };
        #pragma unroll
        for (int i = 0; i < ITEMS; ++i)
            if (tv[i] != 0) tmask |= (1u << i);
    } else {
        #pragma unroll
        for (int i = 0; i < ITEMS; ++i) {
            long long g = cs + i;
            if (g < (long long)n) {
                r[i] = reward[g];
                if (term[g] != 0) tmask |= (1u << i);
            } else { r[i] = 0.0f; onemask |= (1u << i); }
        }
    }

    if (extFull) {
        float2 hv = *(const float2*)(reward + hs);
        int2   hw = *(const int2*)(term + hs);
        hr[0] = hv.x; hr[1] = hv.y;
        if (hw.x != 0) htmask |= 1u;
        if (hw.y != 0) htmask |= 2u;
    } else {
        #pragma unroll
        for (int i = 0; i < HITEMS; ++i) {
            long long g = hs + i;
            if (g < (long long)n) {
                hr[i] = reward[g];
                if (term[g] != 0) htmask |= (1u << i);
            } else { hr[i] = 0.0f; honemask |= (1u << i); }
        }
    }

    // ---------------- halo per-thread affine + warp suffix-compose ----------------
    float hA = 1.0f, hB;
    {
        float y = 0.0f;
        #pragma unroll
        for (int i = HITEMS - 1; i >= 0; --i) {
            float a = ((htmask >> i) & 1u) ? 0.0f : (((honemask >> i) & 1u) ? 1.0f : DISC);
            y = fmaf(a, y, hr[i]);
            hA *= a;
        }
        hB = y;
    }
    #pragma unroll
    for (int d = 1; d < 32; d <<= 1) {
        float a2 = __shfl_down_sync(FULLMASK, hA, d);
        float b2 = __shfl_down_sync(FULLMASK, hB, d);
        if (lane + d < 32) { hB = fmaf(hA, b2, hB); hA = hA * a2; }
    }

    // ---------------- owned pass 1: zero-carry values + chunk affine ----------------
    float A, B;
    if (ownFull) {
        // 4 independent 4-item Horner chains (zero carry at each quarter end)
        #pragma unroll
        for (int q = 0; q < 4; ++q) {
            float y = 0.0f;
            #pragma unroll
            for (int i = 3; i >= 0; --i) {
                const int idx = 4 * q + i;
                float yp = ((tmask >> idx) & 1u) ? 0.0f : y;
                y = fmaf(DISC, yp, r[idx]);
                r[idx] = y;                      // value with zero carry at quarter end
            }
        }
        // quarter coefficients (closed form) + carry chain across quarters
        float A2 = ((tmask >> 8) & 0xFu) ? 0.0f : pw[4];
        float A1 = ((tmask >> 4) & 0xFu) ? 0.0f : pw[4];
        float V3 = r[12];                        // value at item 12, zero chunk carry
        float V2 = fmaf(A2, V3, r[8]);
        float V1 = fmaf(A1, V2, r[4]);
        // fix quarters 0..2 with their incoming carries (quarter 3 has carry 0)
        #pragma unroll
        for (int q = 0; q < 3; ++q) {
            const float Cq = (q == 0) ? V1 : (q == 1) ? V2 : V3;
            #pragma unroll
            for (int i = 0; i < 4; ++i) {
                const int idx = 4 * q + i;
                unsigned bits = (tmask >> idx) & ((1u << (4 - i)) - 1u);  // bits idx..4q+3
                float P = bits ? 0.0f : pw[4 - i];
                r[idx] = fmaf(P, Cq, r[idx]);    // now zero-CHUNK-carry value
            }
        }
        B = r[0];
        A = tmask ? 0.0f : pw[16];
    } else {
        float y = 0.0f; A = 1.0f;
        #pragma unroll
        for (int i = ITEMS - 1; i >= 0; --i) {
            float a = ((tmask >> i) & 1u) ? 0.0f : (((onemask >> i) & 1u) ? 1.0f : DISC);
            y = fmaf(a, y, r[i]);
            A *= a;
        }
        B = y;
    }

    // ---------------- warp suffix scan over per-thread (A,B) ----------------
    float Ai = A, Bi = B;
    #pragma unroll
    for (int d = 1; d < 32; d <<= 1) {
        float a2 = __shfl_down_sync(FULLMASK, Ai, d);
        float b2 = __shfl_down_sync(FULLMASK, Bi, d);
        if (lane + d < 32) { Bi = fmaf(Ai, b2, Bi); Ai = Ai * a2; }
    }
    float exA = __shfl_down_sync(FULLMASK, Ai, 1);   // exclusive = inclusive of lane+1
    float exB = __shfl_down_sync(FULLMASK, Bi, 1);
    if (lane == 31) { exA = 1.0f; exB = 0.0f; }

    if (lane == 0) {
        s_wA[wid] = Ai; s_wB[wid] = Bi;
        s_hA[wid] = hA; s_hB[wid] = hB;
    }
    __syncthreads();

    // ---------------- warp 0: cross-warp scans (owned exclusive + halo total) -----
    if (wid == 0) {
        bool v = lane < NWARPS;
        float wa = v ? s_wA[lane] : 1.0f;
        float wb = v ? s_wB[lane] : 0.0f;
        float ha = v ? s_hA[lane] : 1.0f;
        float hb = v ? s_hB[lane] : 0.0f;
        #pragma unroll
        for (int d = 1; d < 32; d <<= 1) {
            float a2 = __shfl_down_sync(FULLMASK, wa, d);
            float b2 = __shfl_down_sync(FULLMASK, wb, d);
            float a3 = __shfl_down_sync(FULLMASK, ha, d);
            float b3 = __shfl_down_sync(FULLMASK, hb, d);
            if (lane + d < 32) {
                wb = fmaf(wa, b2, wb); wa *= a2;
                hb = fmaf(ha, b3, hb); ha *= a3;
            }
        }
        // exclusive owned carry for warp `lane` = inclusive of lane+1 (identity beyond 15)
        float ecA = __shfl_down_sync(FULLMASK, wa, 1);
        float ecB = __shfl_down_sync(FULLMASK, wb, 1);
        if (v) {
            if (lane == NWARPS - 1) { ecA = 1.0f; ecB = 0.0f; }
            s_cA[lane] = ecA; s_cB[lane] = ecB;
        }
        if (lane == 0) s_yin = hb;     // halo composition applied to 0
    }
    __syncthreads();

    const float yin = s_yin;
    const float cA  = s_cA[wid];
    const float cB  = s_cB[wid];
    const float etA = exA * cA;
    const float etB = fmaf(exA, cB, exB);
    const float Yc  = fmaf(etA, yin, etB);    // carry entering this thread's chunk end

    // ---------------- outputs ----------------
    if (ownFull) {
        #pragma unroll
        for (int i = 0; i < ITEMS; ++i) {
            float P = (tmask >> i) ? 0.0f : pw[ITEMS - i];   // independent FFMAs
            r[i] = fmaf(P, Yc, r[i]);
        }
        float4* op = (float4*)(out + cs);
        __stcs(op + 0, make_float4(r[0],  r[1],  r[2],  r[3]));
        __stcs(op + 1, make_float4(r[4],  r[5],  r[6],  r[7]));
        __stcs(op + 2, make_float4(r[8],  r[9],  r[10], r[11]));
        __stcs(op + 3, make_float4(r[12], r[13], r[14], r[15]));
    } else {
        float y = Yc;
        #pragma unroll
        for (int i = ITEMS - 1; i >= 0; --i) {
            float a = ((tmask >> i) & 1u) ? 0.0f : (((onemask >> i) & 1u) ? 1.0f : DISC);
            y = fmaf(a, y, r[i]);
            long long g = cs + i;
            if (g < (long long)n) out[g] = y;
        }
    }
}

extern "C" void kernel_launch(void* const* d_in, const int* in_sizes, int n_in,
                              void* d_out, int out_size)
{
    const int*   term   = (const int*)d_in[0];     // 'terminal' (bool -> int32)
    const float* reward = (const float*)d_in[1];   // 'reward' (f32)
    float*       out    = (float*)d_out;
    int n  = in_sizes[1];
    int nb = (n + TILE - 1) / TILE;                // 2048 for T=16777216
    scan_k<<<nb, THREADS>>>(reward, term, out, n);
}

// round 8
// speedup vs baseline: 1.3786x; 1.0792x over previous
#include <cuda_runtime.h>
#include <cstdint>

#define THREADS  256
#define ITEMS    16
#define TILE     (THREADS * ITEMS)    // 4096
#define HALO     1024
#define HITEMS   (HALO / THREADS)     // 4
#define NWARPS   (THREADS / 32)       // 8
#define FULLMASK 0xFFFFFFFFu
#define DISC     0.99f

// y[t] = a[t]*y[t+1] + r[t],  a = terminal[t] ? 0 : DISC,  y[n] = 0 (FINAL_REWARD=0).
// Halo truncation: carry through 1024 non-terminal steps scales by 0.99^1024=3.4e-5;
// RMS tile contribution ~3e-6 relative (threshold 1e-3). Blocks fully independent.
__global__ void __launch_bounds__(THREADS, 4)
scan_k(const float* __restrict__ reward,
       const int*  __restrict__ term,      // bool materialized as int32 (0/1)
       float*      __restrict__ out, int n)
{
    __shared__ float s_wA[NWARPS], s_wB[NWARPS];   // owned warp aggregates
    __shared__ float s_hA[NWARPS], s_hB[NWARPS];   // halo warp aggregates
    __shared__ float s_cA[NWARPS], s_cB[NWARPS];   // per-warp exclusive carries
    __shared__ float s_yin;

    // 0.99^k, k=0..16 (verified: pw[8]=pw[4]^2, pw[16]=pw[8]^2)
    const float pw[17] = {
        1.0f, 0.99f, 0.9801f, 0.970299f, 0.96059601f,
        0.9509900499f, 0.941480149401f, 0.93206534790699f, 0.9227446944279201f,
        0.9135172474836409f, 0.9043820750088045f, 0.8953382542587165f,
        0.8863848717161293f, 0.8775210229989680f, 0.8687458127689783f,
        0.8600583546412885f, 0.8514577710948756f };

    const int t    = threadIdx.x;
    const int lane = t & 31;
    const int wid  = t >> 5;

    const long long s  = (long long)blockIdx.x * TILE;
    const long long cs = s + (long long)t * ITEMS;           // owned chunk start
    const long long hs = s + TILE + (long long)t * HITEMS;   // halo chunk start

    const bool ownFull = (s + TILE        <= (long long)n);
    const bool extFull = (s + TILE + HALO <= (long long)n);

    // ---------------- loads (front-batched for MLP) ----------------
    float    r[ITEMS];
    unsigned tmask = 0u, onemask = 0u;
    float    hr[HITEMS];
    unsigned htmask = 0u, honemask = 0u;

    if (ownFull) {
        const float4* rp = (const float4*)(reward + cs);
        const int4*   tp = (const int4*)(term + cs);
        float4 v0 = rp[0], v1 = rp[1], v2 = rp[2], v3 = rp[3];
        int4   w0 = tp[0], w1 = tp[1], w2 = tp[2], w3 = tp[3];
        r[0]=v0.x; r[1]=v0.y; r[2]=v0.z; r[3]=v0.w;
        r[4]=v1.x; r[5]=v1.y; r[6]=v1.z; r[7]=v1.w;
        r[8]=v2.x; r[9]=v2.y; r[10]=v2.z; r[11]=v2.w;
        r[12]=v3.x; r[13]=v3.y; r[14]=v3.z; r[15]=v3.w;
        int tv[ITEMS] = { w0.x,w0.y,w0.z,w0.w, w1.x,w1.y,w1.z,w1.w,
                          w2.x,w2.y,w2.z,w2.w, w3.x,w3.y,w3.z,w3.w };
        #pragma unroll
        for (int i = 0; i < ITEMS; ++i)
            if (tv[i] != 0) tmask |= (1u << i);
    } else {
        #pragma unroll
        for (int i = 0; i < ITEMS; ++i) {
            long long g = cs + i;
            if (g < (long long)n) {
                r[i] = reward[g];
                if (term[g] != 0) tmask |= (1u << i);
            } else { r[i] = 0.0f; onemask |= (1u << i); }
        }
    }

    if (extFull) {
        float4 hv = *(const float4*)(reward + hs);
        int4   hw = *(const int4*)(term + hs);
        hr[0]=hv.x; hr[1]=hv.y; hr[2]=hv.z; hr[3]=hv.w;
        int htv[HITEMS] = { hw.x, hw.y, hw.z, hw.w };
        #pragma unroll
        for (int i = 0; i < HITEMS; ++i)
            if (htv[i] != 0) htmask |= (1u << i);
    } else {
        #pragma unroll
        for (int i = 0; i < HITEMS; ++i) {
            long long g = hs + i;
            if (g < (long long)n) {
                hr[i] = reward[g];
                if (term[g] != 0) htmask |= (1u << i);
            } else { hr[i] = 0.0f; honemask |= (1u << i); }
        }
    }

    // ---------------- halo per-thread affine + warp suffix-compose ----------------
    float hA = 1.0f, hB;
    {
        float y = 0.0f;
        #pragma unroll
        for (int i = HITEMS - 1; i >= 0; --i) {
            float a = ((htmask >> i) & 1u) ? 0.0f : (((honemask >> i) & 1u) ? 1.0f : DISC);
            y = fmaf(a, y, hr[i]);
            hA *= a;
        }
        hB = y;
    }
    #pragma unroll
    for (int d = 1; d < 32; d <<= 1) {
        float a2 = __shfl_down_sync(FULLMASK, hA, d);
        float b2 = __shfl_down_sync(FULLMASK, hB, d);
        if (lane + d < 32) { hB = fmaf(hA, b2, hB); hA = hA * a2; }
    }

    // ---------------- owned pass 1: zero-carry values + chunk affine ----------------
    float A, B;
    if (ownFull) {
        // 4 independent 4-item Horner chains (zero carry at each quarter end)
        #pragma unroll
        for (int q = 0; q < 4; ++q) {
            float y = 0.0f;
            #pragma unroll
            for (int i = 3; i >= 0; --i) {
                const int idx = 4 * q + i;
                float yp = ((tmask >> idx) & 1u) ? 0.0f : y;
                y = fmaf(DISC, yp, r[idx]);
                r[idx] = y;                      // value with zero carry at quarter end
            }
        }
        // quarter coefficients (closed form) + carry chain across quarters
        float A2 = ((tmask >> 8) & 0xFu) ? 0.0f : pw[4];
        float A1 = ((tmask >> 4) & 0xFu) ? 0.0f : pw[4];
        float V3 = r[12];                        // value at item 12, zero chunk carry
        float V2 = fmaf(A2, V3, r[8]);
        float V1 = fmaf(A1, V2, r[4]);
        // fix quarters 0..2 with their incoming carries (quarter 3 has carry 0)
        #pragma unroll
        for (int q = 0; q < 3; ++q) {
            const float Cq = (q == 0) ? V1 : (q == 1) ? V2 : V3;
            #pragma unroll
            for (int i = 0; i < 4; ++i) {
                const int idx = 4 * q + i;
                unsigned bits = (tmask >> idx) & ((1u << (4 - i)) - 1u);  // bits idx..4q+3
                float P = bits ? 0.0f : pw[4 - i];
                r[idx] = fmaf(P, Cq, r[idx]);    // now zero-CHUNK-carry value
            }
        }
        B = r[0];
        A = tmask ? 0.0f : pw[16];
    } else {
        float y = 0.0f; A = 1.0f;
        #pragma unroll
        for (int i = ITEMS - 1; i >= 0; --i) {
            float a = ((tmask >> i) & 1u) ? 0.0f : (((onemask >> i) & 1u) ? 1.0f : DISC);
            y = fmaf(a, y, r[i]);
            A *= a;
        }
        B = y;
    }

    // ---------------- warp suffix scan over per-thread (A,B) ----------------
    float Ai = A, Bi = B;
    #pragma unroll
    for (int d = 1; d < 32; d <<= 1) {
        float a2 = __shfl_down_sync(FULLMASK, Ai, d);
        float b2 = __shfl_down_sync(FULLMASK, Bi, d);
        if (lane + d < 32) { Bi = fmaf(Ai, b2, Bi); Ai = Ai * a2; }
    }
    float exA = __shfl_down_sync(FULLMASK, Ai, 1);   // exclusive = inclusive of lane+1
    float exB = __shfl_down_sync(FULLMASK, Bi, 1);
    if (lane == 31) { exA = 1.0f; exB = 0.0f; }

    if (lane == 0) {
        s_wA[wid] = Ai; s_wB[wid] = Bi;
        s_hA[wid] = hA; s_hB[wid] = hB;
    }
    __syncthreads();

    // ---------------- warp 0: cross-warp scans (owned exclusive + halo total) -----
    if (wid == 0) {
        bool v = lane < NWARPS;
        float wa = v ? s_wA[lane] : 1.0f;
        float wb = v ? s_wB[lane] : 0.0f;
        float ha = v ? s_hA[lane] : 1.0f;
        float hb = v ? s_hB[lane] : 0.0f;
        #pragma unroll
        for (int d = 1; d < 32; d <<= 1) {
            float a2 = __shfl_down_sync(FULLMASK, wa, d);
            float b2 = __shfl_down_sync(FULLMASK, wb, d);
            float a3 = __shfl_down_sync(FULLMASK, ha, d);
            float b3 = __shfl_down_sync(FULLMASK, hb, d);
            if (lane + d < 32) {
                wb = fmaf(wa, b2, wb); wa *= a2;
                hb = fmaf(ha, b3, hb); ha *= a3;
            }
        }
        // exclusive owned carry for warp `lane` = inclusive of lane+1 (identity beyond)
        float ecA = __shfl_down_sync(FULLMASK, wa, 1);
        float ecB = __shfl_down_sync(FULLMASK, wb, 1);
        if (v) {
            if (lane == NWARPS - 1) { ecA = 1.0f; ecB = 0.0f; }
            s_cA[lane] = ecA; s_cB[lane] = ecB;
        }
        if (lane == 0) s_yin = hb;     // halo composition applied to 0
    }
    __syncthreads();

    const float yin = s_yin;
    const float cA  = s_cA[wid];
    const float cB  = s_cB[wid];
    const float etA = exA * cA;
    const float etB = fmaf(exA, cB, exB);
    const float Yc  = fmaf(etA, yin, etB);    // carry entering this thread's chunk

    // ---------------- outputs ----------------
    if (ownFull) {
        #pragma unroll
        for (int i = 0; i < ITEMS; ++i) {
            float P = (tmask >> i) ? 0.0f : pw[ITEMS - i];   // independent FFMAs
            r[i] = fmaf(P, Yc, r[i]);
        }
        float4* op = (float4*)(out + cs);
        __stcs(op + 0, make_float4(r[0],  r[1],  r[2],  r[3]));
        __stcs(op + 1, make_float4(r[4],  r[5],  r[6],  r[7]));
        __stcs(op + 2, make_float4(r[8],  r[9],  r[10], r[11]));
        __stcs(op + 3, make_float4(r[12], r[13], r[14], r[15]));
    } else {
        float y = Yc;
        #pragma unroll
        for (int i = ITEMS - 1; i >= 0; --i) {
            float a = ((tmask >> i) & 1u) ? 0.0f : (((onemask >> i) & 1u) ? 1.0f : DISC);
            y = fmaf(a, y, r[i]);
            long long g = cs + i;
            if (g < (long long)n) out[g] = y;
        }
    }
}

extern "C" void kernel_launch(void* const* d_in, const int* in_sizes, int n_in,
                              void* d_out, int out_size)
{
    const int*   term   = (const int*)d_in[0];     // 'terminal' (bool -> int32)
    const float* reward = (const float*)d_in[1];   // 'reward' (f32)
    float*       out    = (float*)d_out;
    int n  = in_sizes[1];
    int nb = (n + TILE - 1) / TILE;                // 4096 for T=16777216
    scan_k<<<nb, THREADS>>>(reward, term, out, n);
}

// round 9
// speedup vs baseline: 1.4826x; 1.0754x over previous
#include <cuda_runtime.h>
#include <cstdint>

#define THREADS  256
#define ITEMS    16
#define TILE     (THREADS * ITEMS)    // 4096
#define HALO     1024
#define HITEMS   (HALO / THREADS)     // 4
#define NWARPS   (THREADS / 32)       // 8
#define FULLMASK 0xFFFFFFFFu
#define DISC     0.99f

// y[t] = a[t]*y[t+1] + r[t],  a = terminal[t] ? 0 : DISC,  y[n] = 0 (FINAL_REWARD=0).
// Halo truncation: carry through 1024 non-terminal steps scales by 0.99^1024=3.4e-5;
// RMS tile contribution ~2e-6 relative (threshold 1e-3). Blocks fully independent.
__global__ void __launch_bounds__(THREADS, 5)
scan_k(const float* __restrict__ reward,
       const int*  __restrict__ term,      // bool materialized as int32 (0/1)
       float*      __restrict__ out, int n)
{
    __shared__ float s_wA[NWARPS], s_wB[NWARPS];   // owned warp aggregates
    __shared__ float s_hA[NWARPS], s_hB[NWARPS];   // halo warp aggregates
    __shared__ float s_cA[NWARPS], s_cB[NWARPS];   // per-warp exclusive carries
    __shared__ float s_yin;

    // 0.99^k, k=0..16 (pw[8]=pw[4]^2, pw[16]=pw[8]^2)
    const float pw[17] = {
        1.0f, 0.99f, 0.9801f, 0.970299f, 0.96059601f,
        0.9509900499f, 0.941480149401f, 0.93206534790699f, 0.9227446944279201f,
        0.9135172474836409f, 0.9043820750088045f, 0.8953382542587165f,
        0.8863848717161293f, 0.8775210229989680f, 0.8687458127689783f,
        0.8600583546412885f, 0.8514577710948756f };

    const int t    = threadIdx.x;
    const int lane = t & 31;
    const int wid  = t >> 5;

    const int s  = (int)blockIdx.x * TILE;       // n <= ~2^27 here; int is safe
    const int cs = s + t * ITEMS;                // owned chunk start
    const int hs = s + TILE + t * HITEMS;        // halo chunk start

    const bool ownFull = (s + TILE        <= n);
    const bool extFull = (s + TILE + HALO <= n);

    // ---------------- loads (front-batched for MLP) ----------------
    float    r[ITEMS];
    unsigned tmask = 0u, onemask = 0u;
    float    hr[HITEMS];
    unsigned htmask = 0u, honemask = 0u;

    if (ownFull) {
        const float4* rp = (const float4*)(reward + cs);
        const int4*   tp = (const int4*)(term + cs);
        float4 v0 = rp[0], v1 = rp[1], v2 = rp[2], v3 = rp[3];
        int4   w0 = tp[0], w1 = tp[1], w2 = tp[2], w3 = tp[3];
        r[0]=v0.x; r[1]=v0.y; r[2]=v0.z; r[3]=v0.w;
        r[4]=v1.x; r[5]=v1.y; r[6]=v1.z; r[7]=v1.w;
        r[8]=v2.x; r[9]=v2.y; r[10]=v2.z; r[11]=v2.w;
        r[12]=v3.x; r[13]=v3.y; r[14]=v3.z; r[15]=v3.w;
        int tv[ITEMS] = { w0.x,w0.y,w0.z,w0.w, w1.x,w1.y,w1.z,w1.w,
                          w2.x,w2.y,w2.z,w2.w, w3.x,w3.y,w3.z,w3.w };
        #pragma unroll
        for (int i = 0; i < ITEMS; ++i)
            if (tv[i] != 0) tmask |= (1u << i);
    } else {
        #pragma unroll
        for (int i = 0; i < ITEMS; ++i) {
            int g = cs + i;
            if (g < n) {
                r[i] = reward[g];
                if (term[g] != 0) tmask |= (1u << i);
            } else { r[i] = 0.0f; onemask |= (1u << i); }
        }
    }

    if (extFull) {
        float4 hv = *(const float4*)(reward + hs);
        int4   hw = *(const int4*)(term + hs);
        hr[0]=hv.x; hr[1]=hv.y; hr[2]=hv.z; hr[3]=hv.w;
        int htv[HITEMS] = { hw.x, hw.y, hw.z, hw.w };
        #pragma unroll
        for (int i = 0; i < HITEMS; ++i)
            if (htv[i] != 0) htmask |= (1u << i);
    } else {
        #pragma unroll
        for (int i = 0; i < HITEMS; ++i) {
            int g = hs + i;
            if (g < n) {
                hr[i] = reward[g];
                if (term[g] != 0) htmask |= (1u << i);
            } else { hr[i] = 0.0f; honemask |= (1u << i); }
        }
    }

    // ---------------- halo per-thread affine + warp suffix-compose ----------------
    float hA = 1.0f, hB;
    {
        float y = 0.0f;
        #pragma unroll
        for (int i = HITEMS - 1; i >= 0; --i) {
            float a = ((htmask >> i) & 1u) ? 0.0f : (((honemask >> i) & 1u) ? 1.0f : DISC);
            y = fmaf(a, y, hr[i]);
            hA *= a;
        }
        hB = y;
    }
    #pragma unroll
    for (int d = 1; d < 32; d <<= 1) {
        float a2 = __shfl_down_sync(FULLMASK, hA, d);
        float b2 = __shfl_down_sync(FULLMASK, hB, d);
        if (lane + d < 32) { hB = fmaf(hA, b2, hB); hA = hA * a2; }
    }

    // ---------------- owned pass 1: zero-carry values + chunk affine ----------------
    float A, B;
    if (ownFull) {
        // 4 independent 4-item Horner chains (zero carry at each quarter end)
        #pragma unroll
        for (int q = 0; q < 4; ++q) {
            float y = 0.0f;
            #pragma unroll
            for (int i = 3; i >= 0; --i) {
                const int idx = 4 * q + i;
                float yp = ((tmask >> idx) & 1u) ? 0.0f : y;
                y = fmaf(DISC, yp, r[idx]);
                r[idx] = y;                      // value with zero carry at quarter end
            }
        }
        // quarter coefficients (closed form) + carry chain across quarters
        float A2 = ((tmask >> 8) & 0xFu) ? 0.0f : pw[4];
        float A1 = ((tmask >> 4) & 0xFu) ? 0.0f : pw[4];
        float V3 = r[12];                        // value at item 12, zero chunk carry
        float V2 = fmaf(A2, V3, r[8]);
        float V1 = fmaf(A1, V2, r[4]);
        // fix quarters 0..2 with their incoming carries (quarter 3 has carry 0)
        #pragma unroll
        for (int q = 0; q < 3; ++q) {
            const float Cq = (q == 0) ? V1 : (q == 1) ? V2 : V3;
            #pragma unroll
            for (int i = 0; i < 4; ++i) {
                const int idx = 4 * q + i;
                unsigned bits = (tmask >> idx) & ((1u << (4 - i)) - 1u);  // bits idx..4q+3
                float P = bits ? 0.0f : pw[4 - i];
                r[idx] = fmaf(P, Cq, r[idx]);    // now zero-CHUNK-carry value
            }
        }
        B = r[0];
        A = tmask ? 0.0f : pw[16];
    } else {
        float y = 0.0f; A = 1.0f;
        #pragma unroll
        for (int i = ITEMS - 1; i >= 0; --i) {
            float a = ((tmask >> i) & 1u) ? 0.0f : (((onemask >> i) & 1u) ? 1.0f : DISC);
            y = fmaf(a, y, r[i]);
            A *= a;
        }
        B = y;
    }

    // ---------------- warp suffix scan over per-thread (A,B) ----------------
    float Ai = A, Bi = B;
    #pragma unroll
    for (int d = 1; d < 32; d <<= 1) {
        float a2 = __shfl_down_sync(FULLMASK, Ai, d);
        float b2 = __shfl_down_sync(FULLMASK, Bi, d);
        if (lane + d < 32) { Bi = fmaf(Ai, b2, Bi); Ai = Ai * a2; }
    }
    float exA = __shfl_down_sync(FULLMASK, Ai, 1);   // exclusive = inclusive of lane+1
    float exB = __shfl_down_sync(FULLMASK, Bi, 1);
    if (lane == 31) { exA = 1.0f; exB = 0.0f; }

    if (lane == 0) {
        s_wA[wid] = Ai; s_wB[wid] = Bi;
        s_hA[wid] = hA; s_hB[wid] = hB;
    }
    __syncthreads();

    // ---------------- warp 0: cross-warp scans (owned exclusive + halo total) -----
    if (wid == 0) {
        bool v = lane < NWARPS;
        float wa = v ? s_wA[lane] : 1.0f;
        float wb = v ? s_wB[lane] : 0.0f;
        float ha = v ? s_hA[lane] : 1.0f;
        float hb = v ? s_hB[lane] : 0.0f;
        #pragma unroll
        for (int d = 1; d < 32; d <<= 1) {
            float a2 = __shfl_down_sync(FULLMASK, wa, d);
            float b2 = __shfl_down_sync(FULLMASK, wb, d);
            float a3 = __shfl_down_sync(FULLMASK, ha, d);
            float b3 = __shfl_down_sync(FULLMASK, hb, d);
            if (lane + d < 32) {
                wb = fmaf(wa, b2, wb); wa *= a2;
                hb = fmaf(ha, b3, hb); ha *= a3;
            }
        }
        // exclusive owned carry for warp `lane` = inclusive of lane+1 (identity beyond)
        float ecA = __shfl_down_sync(FULLMASK, wa, 1);
        float ecB = __shfl_down_sync(FULLMASK, wb, 1);
        if (v) {
            if (lane == NWARPS - 1) { ecA = 1.0f; ecB = 0.0f; }
            s_cA[lane] = ecA; s_cB[lane] = ecB;
        }
        if (lane == 0) s_yin = hb;     // halo composition applied to 0
    }
    __syncthreads();

    const float yin = s_yin;
    const float cA  = s_cA[wid];
    const float cB  = s_cB[wid];
    const float etA = exA * cA;
    const float etB = fmaf(exA, cB, exB);
    const float Yc  = fmaf(etA, yin, etB);    // carry entering this thread's chunk

    // ---------------- outputs ----------------
    if (ownFull) {
        #pragma unroll
        for (int i = 0; i < ITEMS; ++i) {
            float P = (tmask >> i) ? 0.0f : pw[ITEMS - i];   // independent FFMAs
            r[i] = fmaf(P, Yc, r[i]);
        }
        float4* op = (float4*)(out + cs);
        __stcs(op + 0, make_float4(r[0],  r[1],  r[2],  r[3]));
        __stcs(op + 1, make_float4(r[4],  r[5],  r[6],  r[7]));
        __stcs(op + 2, make_float4(r[8],  r[9],  r[10], r[11]));
        __stcs(op + 3, make_float4(r[12], r[13], r[14], r[15]));
    } else {
        float y = Yc;
        #pragma unroll
        for (int i = ITEMS - 1; i >= 0; --i) {
            float a = ((tmask >> i) & 1u) ? 0.0f : (((onemask >> i) & 1u) ? 1.0f : DISC);
            y = fmaf(a, y, r[i]);
            int g = cs + i;
            if (g < n) out[g] = y;
        }
    }
}

extern "C" void kernel_launch(void* const* d_in, const int* in_sizes, int n_in,
                              void* d_out, int out_size)
{
    const int*   term   = (const int*)d_in[0];     // 'terminal' (bool -> int32)
    const float* reward = (const float*)d_in[1];   // 'reward' (f32)
    float*       out    = (float*)d_out;
    int n  = in_sizes[1];
    int nb = (n + TILE - 1) / TILE;                // 4096 for T=16777216
    scan_k<<<nb, THREADS>>>(reward, term, out, n);
}